// round 4
// baseline (speedup 1.0000x reference)
#include <cuda_runtime.h>
#include <cstddef>

// Problem constants
#define BB 16      // batch
#define TT 2048    // text len
#define EE 768     // embed dim
#define SS 32      // num sentences
#define LL 64      // max sent len
#define NT 16      // t-chunks for pooling pass
#define TCH (TT / NT)   // 128 timesteps per chunk
#define JC 8       // rows (j) per gather block

// Scratch (no device allocation allowed -> __device__ globals)
__device__ float g_partial[BB * NT * EE];   // partial sums per (b, chunk, e)
__device__ int   g_start[BB * SS];
__device__ int   g_len[BB * SS];

// ---------------------------------------------------------------------------
// Kernel 1: streaming partial mean-pool over T.
// grid = BB*NT blocks, 256 threads; each thread owns e, e+256, e+512.
// Fully coalesced: for fixed t, threads read 1KB contiguous per accumulator.
// ---------------------------------------------------------------------------
__global__ __launch_bounds__(256) void k_pool(const float* __restrict__ in) {
    const int blk = blockIdx.x;
    const int b = blk / NT;
    const int c = blk % NT;
    const int e = threadIdx.x;  // 0..255

    const float* base = in + ((size_t)b * TT + (size_t)c * TCH) * EE;

    float a0 = 0.f, a1 = 0.f, a2 = 0.f;
#pragma unroll 4
    for (int t = 0; t < TCH; t++) {
        const float* p = base + (size_t)t * EE;
        a0 += p[e];
        a1 += p[e + 256];
        a2 += p[e + 512];
    }
    float* out = g_partial + (size_t)(b * NT + c) * EE;
    out[e]       = a0;
    out[e + 256] = a1;
    out[e + 512] = a2;
}

// ---------------------------------------------------------------------------
// Kernel 2: finish mean (double reduce of 16 partials), tiny GEMM
// offsets = pooled @ W + b, then exact index math matching the reference:
//   start_off = (int)clip(off_s, 0, 63)        (truncation == floor, nonneg)
//   end_off   = (int)clip(off_{s+32}, 0, 63)
//   start_idx = clip(s*64 + start_off, 0, T-L)
//   end_idx   = clip(s*64 + 64 + end_off, start_idx, T)
// grid = BB blocks, 256 threads (only first 32 do the dots).
// ---------------------------------------------------------------------------
__global__ __launch_bounds__(256) void k_idx(const float* __restrict__ W,
                                             const float* __restrict__ bias) {
    const int b = blockIdx.x;
    const int tid = threadIdx.x;
    __shared__ float pooled[EE];

#pragma unroll
    for (int k = 0; k < 3; k++) {
        const int e = tid + 256 * k;
        double acc = 0.0;
#pragma unroll
        for (int c = 0; c < NT; c++)
            acc += (double)g_partial[(size_t)(b * NT + c) * EE + e];
        pooled[e] = (float)(acc / (double)TT);
    }
    __syncthreads();

    if (tid < SS) {
        const int s = tid;
        float d1 = 0.f, d2 = 0.f;
        for (int e = 0; e < EE; e++) {
            const float p = pooled[e];
            d1 = fmaf(p, W[e * (2 * SS) + s], d1);
            d2 = fmaf(p, W[e * (2 * SS) + s + SS], d2);
        }
        const float off1 = d1 + bias[s];
        const float off2 = d2 + bias[s + SS];

        const int so = (int)fminf(fmaxf(off1, 0.f), (float)(LL - 1));
        const int eo = (int)fminf(fmaxf(off2, 0.f), (float)(LL - 1));

        const int basei = s * LL;
        int start = basei + so;
        if (start > TT - LL) start = TT - LL;
        if (start < 0) start = 0;
        int end = basei + LL + eo;
        if (end < start) end = start;
        if (end > TT) end = TT;

        g_start[b * SS + s] = start;
        g_len[b * SS + s]   = end - start;   // j valid while j < len (j < 64 implied)
    }
}

// ---------------------------------------------------------------------------
// Kernel 3: vectorized gather+pad.
// grid = BB*SS*(LL/JC) = 4096 blocks, 192 threads (768 floats = 192 float4).
// Each block handles 8 output rows (j) of one sentence -> 8 independent
// float4 loads in flight per thread after unroll. Input rows should be L2-hot
// from k_pool (100MB input < 126MB L2). Invalid rows write zeros.
// ---------------------------------------------------------------------------
__global__ __launch_bounds__(192) void k_gather(const float* __restrict__ in,
                                                float* __restrict__ out) {
    const int idx = blockIdx.x;
    const int jc = idx & (LL / JC - 1);          // 0..7
    const int s  = (idx >> 3) & (SS - 1);        // 0..31
    const int b  = idx >> 8;                     // 0..15
    const int tid = threadIdx.x;                 // 0..191

    const int start = g_start[b * SS + s];
    const int len   = g_len[b * SS + s];

    const float4* src_base =
        (const float4*)(in + ((size_t)b * TT + (size_t)start) * EE);
    float4* dst_base =
        (float4*)(out + ((size_t)(b * SS + s) * LL) * EE);

    const int j0 = jc * JC;
#pragma unroll
    for (int jj = 0; jj < JC; jj++) {
        const int j = j0 + jj;
        float4 v = make_float4(0.f, 0.f, 0.f, 0.f);
        if (j < len)
            v = src_base[(size_t)j * (EE / 4) + tid];
        dst_base[(size_t)j * (EE / 4) + tid] = v;
    }
}

// ---------------------------------------------------------------------------
// Entry point. Inputs (metadata order): inputs f32 [B,T,E], W f32 [E,2S],
// b f32 [2S]. Output f32 [B,S,L,E].
// ---------------------------------------------------------------------------
extern "C" void kernel_launch(void* const* d_in, const int* in_sizes, int n_in,
                              void* d_out, int out_size) {
    const float* in   = (const float*)d_in[0];
    const float* W    = (const float*)d_in[1];
    const float* bias = (const float*)d_in[2];
    float* out        = (float*)d_out;

    k_pool<<<BB * NT, 256>>>(in);
    k_idx<<<BB, 256>>>(W, bias);
    k_gather<<<BB * SS * (LL / JC), 192>>>(in, out);
}

// round 5
// speedup vs baseline: 1.9606x; 1.9606x over previous
#include <cuda_runtime.h>
#include <cstddef>

// Problem constants
#define BB 16      // batch
#define TT 2048    // text len
#define EE 768     // embed dim
#define E4 (EE/4)  // 192 float4 per row
#define SS 32      // num sentences
#define LL 64      // max sent len
#define NT 64      // t-chunks for pooling pass
#define TCH (TT / NT)   // 32 timesteps per chunk
#define JC 8       // rows (j) per gather block

// Scratch (no device allocation allowed -> __device__ globals)
__device__ float4 g_partial4[BB * NT * E4];  // partial sums per (b, chunk, e4)
__device__ int    g_start[BB * SS];
__device__ int    g_len[BB * SS];

// ---------------------------------------------------------------------------
// Kernel 1: streaming partial mean-pool over T. float4, high MLP.
// grid = BB*NT = 1024 blocks, 192 threads; thread owns one float4 column.
// 32 independent LDG.128 per thread (unrolled), FADD chains only 4cyc deep.
// ---------------------------------------------------------------------------
__global__ __launch_bounds__(192) void k_pool(const float4* __restrict__ in) {
    const int blk = blockIdx.x;
    const int b = blk / NT;
    const int c = blk % NT;
    const int e4 = threadIdx.x;  // 0..191

    const float4* base = in + ((size_t)b * TT + (size_t)c * TCH) * E4 + e4;

    float4 a0 = make_float4(0.f, 0.f, 0.f, 0.f);
    float4 a1 = make_float4(0.f, 0.f, 0.f, 0.f);
#pragma unroll 8
    for (int t = 0; t < TCH; t += 2) {
        float4 v0 = base[(size_t)t * E4];
        float4 v1 = base[(size_t)(t + 1) * E4];
        a0.x += v0.x; a0.y += v0.y; a0.z += v0.z; a0.w += v0.w;
        a1.x += v1.x; a1.y += v1.y; a1.z += v1.z; a1.w += v1.w;
    }
    float4 s;
    s.x = a0.x + a1.x; s.y = a0.y + a1.y; s.z = a0.z + a1.z; s.w = a0.w + a1.w;
    g_partial4[(size_t)(b * NT + c) * E4 + e4] = s;
}

// ---------------------------------------------------------------------------
// Kernel 2: finish mean, tiny GEMM offsets = pooled @ W + b, index math.
// grid = BB blocks, 256 threads.
//  Phase A: 192 threads reduce 64 float4 partials each -> pooled[768] in smem.
//  Phase B: 256 threads = 64 columns x 4 e-segments of 192; shared reduce.
// Index math matches reference exactly:
//   start_off = (int)clip(off_s, 0, 63); end_off = (int)clip(off_{s+32},0,63)
//   start = clip(s*64+start_off, 0, T-L); end = clip(s*64+64+end_off, start, T)
// ---------------------------------------------------------------------------
__global__ __launch_bounds__(256) void k_idx(const float* __restrict__ W,
                                             const float* __restrict__ bias) {
    const int b = blockIdx.x;
    const int tid = threadIdx.x;
    __shared__ float pooled[EE];
    __shared__ float red[4][2 * SS];

    if (tid < E4) {
        const float4* p = g_partial4 + (size_t)b * NT * E4 + tid;
        float4 a0 = make_float4(0.f, 0.f, 0.f, 0.f);
        float4 a1 = make_float4(0.f, 0.f, 0.f, 0.f);
#pragma unroll
        for (int c = 0; c < NT; c += 2) {
            float4 v0 = p[(size_t)c * E4];
            float4 v1 = p[(size_t)(c + 1) * E4];
            a0.x += v0.x; a0.y += v0.y; a0.z += v0.z; a0.w += v0.w;
            a1.x += v1.x; a1.y += v1.y; a1.z += v1.z; a1.w += v1.w;
        }
        const float inv = 1.0f / (float)TT;
        pooled[4 * tid + 0] = (a0.x + a1.x) * inv;
        pooled[4 * tid + 1] = (a0.y + a1.y) * inv;
        pooled[4 * tid + 2] = (a0.z + a1.z) * inv;
        pooled[4 * tid + 3] = (a0.w + a1.w) * inv;
    }
    __syncthreads();

    // Phase B: col = tid & 63, segment g = tid >> 6 (0..3), 192 elems each.
    {
        const int col = tid & (2 * SS - 1);
        const int g = tid >> 6;
        float acc = 0.f;
        const int e0 = g * 192;
#pragma unroll 8
        for (int e = e0; e < e0 + 192; e++)
            acc = fmaf(pooled[e], W[e * (2 * SS) + col], acc);
        red[g][col] = acc;
    }
    __syncthreads();

    if (tid < SS) {
        const int s = tid;
        const float off1 = red[0][s] + red[1][s] + red[2][s] + red[3][s] + bias[s];
        const float off2 = red[0][s + SS] + red[1][s + SS] + red[2][s + SS] +
                           red[3][s + SS] + bias[s + SS];

        const int so = (int)fminf(fmaxf(off1, 0.f), (float)(LL - 1));
        const int eo = (int)fminf(fmaxf(off2, 0.f), (float)(LL - 1));

        const int basei = s * LL;
        int start = basei + so;
        if (start > TT - LL) start = TT - LL;
        if (start < 0) start = 0;
        int end = basei + LL + eo;
        if (end < start) end = start;
        if (end > TT) end = TT;

        g_start[b * SS + s] = start;
        g_len[b * SS + s]   = end - start;
    }
}

// ---------------------------------------------------------------------------
// Kernel 3: vectorized gather+pad.
// grid = BB*SS*(LL/JC) = 4096 blocks, 192 threads.
// Batched: 8 independent LDG.128 issued before any store (MLP=8/thread),
// then 8 streaming stores (__stcs) so output doesn't evict the L2-resident
// input left behind by k_pool.
// ---------------------------------------------------------------------------
__global__ __launch_bounds__(192) void k_gather(const float4* __restrict__ in,
                                                float4* __restrict__ out) {
    const int idx = blockIdx.x;
    const int jc = idx & (LL / JC - 1);          // 0..7
    const int s  = (idx >> 3) & (SS - 1);        // 0..31
    const int b  = idx >> 8;                     // 0..15
    const int tid = threadIdx.x;                 // 0..191

    const int start = g_start[b * SS + s];
    const int len   = g_len[b * SS + s];

    const float4* src = in + ((size_t)b * TT + (size_t)start) * E4 + tid;
    float4* dst = out + ((size_t)(b * SS + s) * LL) * E4 + tid;

    const int j0 = jc * JC;
    float4 v[JC];
#pragma unroll
    for (int jj = 0; jj < JC; jj++) {
        const int j = j0 + jj;
        v[jj] = (j < len) ? src[(size_t)j * E4]
                          : make_float4(0.f, 0.f, 0.f, 0.f);
    }
#pragma unroll
    for (int jj = 0; jj < JC; jj++)
        __stcs(&dst[(size_t)(j0 + jj) * E4], v[jj]);
}

// ---------------------------------------------------------------------------
// Entry point. Inputs (metadata order): inputs f32 [B,T,E], W f32 [E,2S],
// b f32 [2S]. Output f32 [B,S,L,E].
// ---------------------------------------------------------------------------
extern "C" void kernel_launch(void* const* d_in, const int* in_sizes, int n_in,
                              void* d_out, int out_size) {
    const float4* in  = (const float4*)d_in[0];
    const float* W    = (const float*)d_in[1];
    const float* bias = (const float*)d_in[2];
    float4* out       = (float4*)d_out;

    k_pool<<<BB * NT, 192>>>(in);
    k_idx<<<BB, 256>>>(W, bias);
    k_gather<<<BB * SS * (LL / JC), 192>>>(in, out);
}